// round 1
// baseline (speedup 1.0000x reference)
#include <cuda_runtime.h>
#include <math.h>

#define D_MODEL   64
#define SEQ       4096
#define BATCH_N   256
#define LUT_N     4096
#define PF        8          // prefetch depth == unroll factor

// fp32 constants matching jax weak-typed promotion (python double -> fp32 scalar)
#define TWOPI_F   6.2831853071795864769f     // rounds to fl32(2*pi)
#define PHI_F     1.6180339887498948482f     // fl32(golden ratio)
#define STEP_F    ((float)(6.283185307179586 / 4096.0))
#define INV2PI_F  (1.0f / 6.2831853071795864769f)
#define MAGIC     12582912.0f                // 2^23 + 2^22: round-down integer extractor

// smem layout (dynamic): lut(32KB) | tok(16KB) | tphi(16KB) | h(512B)
#define SM_LUT_OFF   0
#define SM_TOK_OFF   32768
#define SM_TPHI_OFF  49152
#define SM_H_OFF     65536
#define SM_TOTAL     66048

__global__ void __launch_bounds__(64, 2)
rin_scan_kernel(const int* __restrict__ ids,
                const float* __restrict__ emb,
                const float* __restrict__ projW,
                const float* __restrict__ projB,
                float* __restrict__ out)
{
    extern __shared__ unsigned char smem[];
    float2* s_lut  = (float2*)(smem + SM_LUT_OFF);
    int*    s_tok  = (int*)  (smem + SM_TOK_OFF);
    float*  s_tphi = (float*)(smem + SM_TPHI_OFF);
    float*  s_h    = (float*)(smem + SM_H_OFF);

    const int b = blockIdx.x;
    const int d = threadIdx.x;

    // ---- init: LUT (sin,cos interleaved), token row, t*phi mod 2pi ----
    for (int i = d; i < LUT_N; i += 64) {
        float ang = __fmul_rn(STEP_F, (float)i);
        s_lut[i] = make_float2(sinf(ang), cosf(ang));
    }
    for (int i = d; i < SEQ; i += 64) {
        s_tok[i]  = ids[b * SEQ + i];
        // jnp.mod(arange*PHI, 2pi): positive operands -> exact fmod
        s_tphi[i] = fmodf(__fmul_rn((float)i, PHI_F), TWOPI_F);
    }
    __syncthreads();

    // ---- prefetch first PF steps of embedding data ----
    float w_pf[PF], b_pf[PF];
#pragma unroll
    for (int j = 0; j < PF; j++) {
        int tok = s_tok[j];
        const float* row = emb + (size_t)tok * (2 * D_MODEL) + d;
        w_pf[j] = __ldg(row);
        b_pf[j] = __ldg(row + D_MODEL);
    }

    float hr = 0.0f, hi = 0.0f;

    for (int sb = 0; sb < SEQ; sb += PF) {
#pragma unroll
        for (int j = 0; j < PF; j++) {
            const int s = sb + j;
            const float wv = w_pf[j];
            const float bv = b_pf[j];

            // issue next prefetch (wraps harmlessly on final chunk)
            {
                int sn = (s + PF) & (SEQ - 1);
                int tok = s_tok[sn];
                const float* row = emb + (size_t)tok * (2 * D_MODEL) + d;
                w_pf[j] = __ldg(row);
                b_pf[j] = __ldg(row + D_MODEL);
            }

            // off-critical-path per-step coefficients
            float wl  = __fadd_rn(1.0f, fabsf(wv));
            float inv = __frcp_rn(wl);                 // correctly-rounded 1/wl
            float a   = __fmul_rn(inv, INV2PI_F);      // (1/wl)/(2pi)
            float c2  = __fmul_rn(__fadd_rn(bv, s_tphi[s]), INV2PI_F);

            // ---- critical path: real angle ----
            float xr  = __fmaf_rn(hr, a, c2);                       // theta_r / 2pi
            float fxr = __fsub_rn(__fadd_rd(xr, MAGIC), MAGIC);     // floor(xr)
            float fr  = __fsub_rn(xr, fxr);                         // frac in [0,1]
            float gr  = __fmul_rn(fr, 4096.0f);
            int   ir  = __float_as_int(__fadd_rd(gr, MAGIC)) & 4095; // floor + mod 4096

            // ---- critical path: imag angle (independent, overlaps) ----
            float xi  = __fmaf_rn(hi, a, c2);
            float fxi = __fsub_rn(__fadd_rd(xi, MAGIC), MAGIC);
            float fi  = __fsub_rn(xi, fxi);
            float gi  = __fmul_rn(fi, 4096.0f);
            int   ii  = __float_as_int(__fadd_rd(gi, MAGIC)) & 4095;

            float2 scr = s_lut[ir];   // (sin, cos) at theta_r
            float2 sci = s_lut[ii];   // (sin, cos) at theta_i

            float sr = scr.x, cr = scr.y;
            float si = sci.x, ci = sci.y;

            // h_new = (cr*ci - sr*si, cr*si + sr*ci) with non-fused mul/add like XLA
            hr = __fsub_rn(__fmul_rn(cr, ci), __fmul_rn(sr, si));
            hi = __fadd_rn(__fmul_rn(cr, si), __fmul_rn(sr, ci));
        }
    }

    // ---- projection: out[b,n] = sum_k h[k]*W[n,k] + bias[n] ----
    s_h[d] = hr;
    s_h[D_MODEL + d] = hi;
    __syncthreads();

    float acc0 = 0.0f, acc1 = 0.0f;
    const float* w0 = projW + (size_t)d * 128;
    const float* w1 = projW + (size_t)(d + 64) * 128;
#pragma unroll 8
    for (int k = 0; k < 128; k++) {
        float hk = s_h[k];
        acc0 = __fmaf_rn(hk, __ldg(w0 + k), acc0);
        acc1 = __fmaf_rn(hk, __ldg(w1 + k), acc1);
    }
    out[(size_t)b * 128 + d]      = __fadd_rn(acc0, __ldg(projB + d));
    out[(size_t)b * 128 + 64 + d] = __fadd_rn(acc1, __ldg(projB + d + 64));
}

extern "C" void kernel_launch(void* const* d_in, const int* in_sizes, int n_in,
                              void* d_out, int out_size)
{
    const int*   ids  = (const int*)d_in[0];     // (256, 4096) int32
    const float* emb  = (const float*)d_in[1];   // (50257, 128) f32
    const float* W    = (const float*)d_in[2];   // (128, 128) f32
    const float* bias = (const float*)d_in[3];   // (128,) f32
    float* out = (float*)d_out;                  // (256, 128) f32

    cudaFuncSetAttribute(rin_scan_kernel,
                         cudaFuncAttributeMaxDynamicSharedMemorySize, SM_TOTAL);
    rin_scan_kernel<<<BATCH_N, D_MODEL, SM_TOTAL>>>(ids, emb, W, bias, out);
}

// round 4
// speedup vs baseline: 2.1576x; 2.1576x over previous
#include <cuda_runtime.h>
#include <math.h>

#define D_MODEL   64
#define SEQ       4096
#define BATCH_N   256
#define VOCAB     50257
#define LUT_N     4096
#define PF        8

#define TWOPI_F   6.2831853071795864769f
#define PHI_F     1.6180339887498948482f
#define STEP_F    ((float)(6.283185307179586 / 4096.0))
#define KSCALE    651.8986469044033f          /* 4096 / (2*pi) */
#define MAGIC     12582912.0f                 /* 2^23 + 2^22 : round-down int extractor */

// Precomputed per-(token, d): x = KSCALE/(1+|w|), y = b*KSCALE  (interleaved for LDG.64)
__device__ float2 g_A[(size_t)VOCAB * D_MODEL];

__global__ void __launch_bounds__(256)
prep_kernel(const float* __restrict__ emb)
{
    int idx = blockIdx.x * 256 + threadIdx.x;
    if (idx >= VOCAB * D_MODEL) return;
    int tok = idx >> 6;
    int d   = idx & 63;
    float w = emb[(size_t)tok * 128 + d];
    float b = emb[(size_t)tok * 128 + 64 + d];
    float a = __fdividef(KSCALE, __fadd_rn(1.0f, fabsf(w)));
    g_A[idx] = make_float2(a, __fmul_rn(b, KSCALE));
}

// smem: lut 32KB | tphiK 16KB | tok[2] 32KB | h[2] 1KB
#define SM_LUT_OFF   0
#define SM_TPHI_OFF  32768
#define SM_TOK_OFF   49152
#define SM_H_OFF     81920
#define SM_TOTAL     82944

__global__ void __launch_bounds__(128, 1)
rin_scan_kernel(const int* __restrict__ ids,
                const float* __restrict__ projW,
                const float* __restrict__ projB,
                float* __restrict__ out)
{
    extern __shared__ unsigned char smem[];
    float2* s_lut   = (float2*)(smem + SM_LUT_OFF);
    float*  s_tphiK = (float*) (smem + SM_TPHI_OFF);
    int*    s_tok   = (int*)   (smem + SM_TOK_OFF);   // [2][4096]
    float*  s_h     = (float*) (smem + SM_H_OFF);     // [2][128]

    const int tid = threadIdx.x;
    const int sub = tid >> 6;           // which batch within the block
    const int d   = tid & 63;
    const int batch = blockIdx.x * 2 + sub;

    // ---- init ----
    for (int i = tid; i < LUT_N; i += 128) {
        float ang = __fmul_rn(STEP_F, (float)i);
        s_lut[i] = make_float2(sinf(ang), cosf(ang));   // (sin, cos)
    }
    for (int i = tid; i < SEQ; i += 128) {
        s_tphiK[i] = __fmul_rn(fmodf(__fmul_rn((float)i, PHI_F), TWOPI_F), KSCALE);
    }
    {
        const int* row = ids + (size_t)batch * SEQ;
        int* st = s_tok + sub * SEQ;
        for (int i = d; i < SEQ; i += 64) st[i] = row[i];
    }
    __syncthreads();

    const int* st = s_tok + sub * SEQ;

    // ---- prefetch first PF steps of (a, b*K) ----
    float2 pf[PF];
#pragma unroll
    for (int j = 0; j < PF; j++)
        pf[j] = __ldg(&g_A[(size_t)st[j] * D_MODEL + d]);

    float hr = 0.0f, hi = 0.0f;   // h = (cos, sin) of tracked phase; starts at (0,0)

    for (int sb = 0; sb < SEQ; sb += PF) {
#pragma unroll
        for (int j = 0; j < PF; j++) {
            const int s = sb + j;
            const float a  = pf[j].x;
            const float bk = pf[j].y;

            // next prefetch (wraps harmlessly at the end)
            {
                int sn = (s + PF) & (SEQ - 1);
                pf[j] = __ldg(&g_A[(size_t)st[sn] * D_MODEL + d]);
            }

            float c  = __fadd_rn(bk, s_tphiK[s]);      // (b + t*phi) * K, off critical path

            // critical path: y in bin units, floor via magic, sum phases, one LDS.64
            float yr = __fmaf_rn(hr, a, c);
            float yi = __fmaf_rn(hi, a, c);
            int   br = __float_as_int(__fadd_rd(yr, MAGIC));
            int   bi = __float_as_int(__fadd_rd(yi, MAGIC));
            int   k  = (br + bi) & (LUT_N - 1);        // (floor(yr)+floor(yi)) mod 4096

            float2 sc = s_lut[k];
            hi = sc.x;                                 // sin(k * 2pi/4096)
            hr = sc.y;                                 // cos(k * 2pi/4096)
        }
    }

    // ---- projection: out[b,n] = sum_k h[k]*W[n,k] + bias[n] ----
    float* sh = s_h + sub * 128;
    sh[d] = hr;
    sh[64 + d] = hi;
    __syncthreads();

    float acc0 = 0.0f, acc1 = 0.0f;
    const float* w0 = projW + (size_t)d * 128;
    const float* w1 = projW + (size_t)(d + 64) * 128;
#pragma unroll 8
    for (int kk = 0; kk < 128; kk++) {
        float hk = sh[kk];
        acc0 = __fmaf_rn(hk, __ldg(w0 + kk), acc0);
        acc1 = __fmaf_rn(hk, __ldg(w1 + kk), acc1);
    }
    out[(size_t)batch * 128 + d]      = __fadd_rn(acc0, __ldg(projB + d));
    out[(size_t)batch * 128 + 64 + d] = __fadd_rn(acc1, __ldg(projB + d + 64));
}

extern "C" void kernel_launch(void* const* d_in, const int* in_sizes, int n_in,
                              void* d_out, int out_size)
{
    const int*   ids  = (const int*)d_in[0];     // (256, 4096) int32
    const float* emb  = (const float*)d_in[1];   // (50257, 128) f32
    const float* W    = (const float*)d_in[2];   // (128, 128) f32
    const float* bias = (const float*)d_in[3];   // (128,) f32
    float* out = (float*)d_out;                  // (256, 128) f32

    prep_kernel<<<(VOCAB * D_MODEL + 255) / 256, 256>>>(emb);

    cudaFuncSetAttribute(rin_scan_kernel,
                         cudaFuncAttributeMaxDynamicSharedMemorySize, SM_TOTAL);
    rin_scan_kernel<<<BATCH_N / 2, 128, SM_TOTAL>>>(ids, W, bias, out);
}